// round 2
// baseline (speedup 1.0000x reference)
#include <cuda_runtime.h>
#include <cuda_fp16.h>
#include <cstdint>

// ---------------- problem constants ----------------
static constexpr int BS    = 32;
static constexpr int RB    = 128;   // row blocks
static constexpr int CBLK  = 128;   // col blocks
static constexpr int NPR   = 13;    // nnz per row block
static constexpr int PAIRS = 7;     // ceil(13/2) col-block pairs (padded)
static constexpr int SLOTS = 14;    // padded nnz slots per row
static constexpr int NCOL  = CBLK * BS;   // 4096
static constexpr int MAXBATCH = 2048;

// ---------------- device scratch (static, no allocation) ----------------
__device__ __align__(16) __half g_x16[(size_t)MAXBATCH * NCOL];          // 16 MB fp16 x
__device__ __align__(16) __half g_wpk[(size_t)RB * PAIRS * 32 * 64];     // 3.5 MB packed, pre-swizzled w
__device__ int g_pcols[RB * SLOTS];

// ---------------- PTX helpers (baseline PTX only: sm_80-era) ----------------
__device__ __forceinline__ uint32_t smem_u32(const void* p) {
    uint32_t a;
    asm("{ .reg .u64 t; cvta.to.shared.u64 t, %1; cvt.u32.u64 %0, t; }" : "=r"(a) : "l"(p));
    return a;
}

__device__ __forceinline__ void cp_async16(uint32_t dst, const void* src) {
    asm volatile("cp.async.cg.shared.global [%0], [%1], 16;" :: "r"(dst), "l"(src));
}
__device__ __forceinline__ void cp_commit() {
    asm volatile("cp.async.commit_group;" ::: "memory");
}
template <int N>
__device__ __forceinline__ void cp_wait() {
    asm volatile("cp.async.wait_group %0;" :: "n"(N) : "memory");
}

// ---------------- prep kernels ----------------
__global__ void k_convert_x(const float* __restrict__ x, int n8) {
    int i = blockIdx.x * blockDim.x + threadIdx.x;
    if (i >= n8) return;
    const float4* x4 = reinterpret_cast<const float4*>(x);
    float4 a = x4[2 * i], b = x4[2 * i + 1];
    union { __half2 h2[4]; uint4 v; } u;
    u.h2[0] = __floats2half2_rn(a.x, a.y);
    u.h2[1] = __floats2half2_rn(a.z, a.w);
    u.h2[2] = __floats2half2_rn(b.x, b.y);
    u.h2[3] = __floats2half2_rn(b.z, b.w);
    reinterpret_cast<uint4*>(g_x16)[i] = u.v;
}

__global__ void k_prep_cols(const int* __restrict__ crow, const int* __restrict__ cols) {
    int i = blockIdx.x * blockDim.x + threadIdx.x;
    if (i >= RB * SLOTS) return;
    int r = i / SLOTS, s = i % SLOTS;
    int beg = crow[r];
    int len = crow[r + 1] - beg;
    g_pcols[i] = (s < len) ? cols[beg + s] : 0;
}

// Packed, masked, fp16, SW128-pre-swizzled weights:
// g_wpk: per (rblk, pair) a 4KB tile: 32 rows (output n) x 128 bytes (64 halves of K
// covering two consecutive nnz col-blocks), swizzled relative to tile base.
__global__ void k_prep_w(const float* __restrict__ mask, const float* __restrict__ w,
                         const int* __restrict__ crow) {
    int tile = blockIdx.x;             // rblk*PAIRS + p
    int rblk = tile / PAIRS, p = tile % PAIRS;
    int q = threadIdx.x;               // 0..255, one 16B chunk each
    int n = q >> 3;                    // output row 0..31
    int m = q & 7;                     // 16B chunk within the 128B row
    int s = m >> 2;                    // which nnz block of the pair
    int kib = (m & 3) * 8;             // k within the 32-wide block
    int beg = crow[rblk];
    int len = crow[rblk + 1] - beg;
    int slot = 2 * p + s;
    bool valid = slot < len;
    long j = beg + slot;
    union { __half h[8]; uint4 v; } u;
#pragma unroll
    for (int i = 0; i < 8; i++) {
        float f = 0.0f;
        if (valid) {
            long e = j * 1024 + n * 32 + kib + i;
            f = mask[e] * w[e];
        }
        u.h[i] = __float2half_rn(f);
    }
    uint32_t off = (uint32_t)(n * 128 + m * 16);
    uint32_t sw = off ^ ((off >> 3) & 0x70);
    char* dst = reinterpret_cast<char*>(g_wpk) + (size_t)tile * 4096 + sw;
    *reinterpret_cast<uint4*>(dst) = u.v;
}

// ---------------- main kernel ----------------
static constexpr int SMEM_A0    = 0;
static constexpr int A_STRIDE   = 128 * 128;                    // 16 KB / stage
static constexpr int SMEM_B0    = SMEM_A0 + PAIRS * A_STRIDE;   // 114688
static constexpr int B_STRIDE   = 32 * 128;                     // 4 KB / stage
static constexpr int SMEM_TOTAL = SMEM_B0 + PAIRS * B_STRIDE;   // 143360

// One stage: wait for its cp.async group, barrier, then K=64 of MMAs.
template <int P>
__device__ __forceinline__ void do_stage(uint32_t sb, int wid, int lane, float acc[4][4]) {
    cp_wait<PAIRS - 1 - P>();
    __syncthreads();
    uint32_t abase = sb + SMEM_A0 + P * A_STRIDE;
    uint32_t bbase = sb + SMEM_B0 + P * B_STRIDE;

    // A ldmatrix.x4 lane addressing: lanes 0-7 rows0-7@k0, 8-15 rows8-15@k0,
    // 16-23 rows0-7@k8, 24-31 rows8-15@k8  ->  regs = a0..a3 of m16n8k16 A frag.
    int arow = lane & 15;
    int akb  = lane >> 4;
    uint32_t aoff0 = (uint32_t)((wid * 16 + arow) * 128 + akb * 16);

    // B ldmatrix.x4 lane addressing: mat0 n0-7@k0, mat1 n0-7@k8, mat2 n8-15@k0, mat3 n8-15@k8.
    int bn  = (lane & 7) + ((lane >> 4) << 3);
    int bkb = (lane >> 3) & 1;

#pragma unroll
    for (int ks = 0; ks < 4; ks++) {
        uint32_t ao = aoff0 + ks * 32;
        uint32_t aaddr = abase + (ao ^ ((ao >> 3) & 0x70));
        uint32_t a0, a1, a2, a3;
        asm volatile("ldmatrix.sync.aligned.m8n8.x4.shared.b16 {%0,%1,%2,%3}, [%4];"
                     : "=r"(a0), "=r"(a1), "=r"(a2), "=r"(a3) : "r"(aaddr));

        uint32_t b[2][4];
#pragma unroll
        for (int h = 0; h < 2; h++) {
            uint32_t bo = (uint32_t)((bn + h * 16) * 128 + ks * 32 + bkb * 16);
            uint32_t baddr = bbase + (bo ^ ((bo >> 3) & 0x70));
            asm volatile("ldmatrix.sync.aligned.m8n8.x4.shared.b16 {%0,%1,%2,%3}, [%4];"
                         : "=r"(b[h][0]), "=r"(b[h][1]), "=r"(b[h][2]), "=r"(b[h][3])
                         : "r"(baddr));
        }

#pragma unroll
        for (int nt = 0; nt < 4; nt++) {
            uint32_t b0 = b[nt >> 1][(nt & 1) * 2 + 0];
            uint32_t b1 = b[nt >> 1][(nt & 1) * 2 + 1];
            asm volatile(
                "mma.sync.aligned.m16n8k16.row.col.f32.f16.f16.f32 "
                "{%0,%1,%2,%3}, {%4,%5,%6,%7}, {%8,%9}, {%0,%1,%2,%3};"
                : "+f"(acc[nt][0]), "+f"(acc[nt][1]), "+f"(acc[nt][2]), "+f"(acc[nt][3])
                : "r"(a0), "r"(a1), "r"(a2), "r"(a3), "r"(b0), "r"(b1));
        }
    }
}

__global__ void __launch_bounds__(256, 1)
k_main(const float* __restrict__ bias, float* __restrict__ out) {
    extern __shared__ char smem[];
    uint32_t sb = smem_u32(smem);
    int tid = threadIdx.x;
    int wid = tid >> 5, lane = tid & 31;
    int mt = blockIdx.x;       // batch tile of 128 rows
    int rblk = blockIdx.y;     // row block

    const __half* xb = g_x16 + (size_t)mt * 128 * NCOL;
    const int* pc = g_pcols + rblk * SLOTS;

    // Prefetch ALL 7 stages up front, one commit group per stage.
#pragma unroll
    for (int p = 0; p < PAIRS; p++) {
        int c0 = __ldg(pc + 2 * p);
        int c1 = __ldg(pc + 2 * p + 1);
        uint32_t abase = sb + SMEM_A0 + p * A_STRIDE;
        // A: 128 rows x 128B (two gathered 32-elem fp16 col blocks), SW128-swizzled.
#pragma unroll
        for (int t = tid; t < 1024; t += 256) {
            int q = t & 3;          // 16B chunk within 64B half
            int h = (t >> 2) & 1;   // which col block of the pair
            int r = t >> 3;         // batch row within tile
            const __half* src = xb + (size_t)r * NCOL + (h ? c1 : c0) * BS + q * 8;
            uint32_t off = (uint32_t)(r * 128 + h * 64 + q * 16);
            uint32_t sw = off ^ ((off >> 3) & 0x70);
            cp_async16(abase + sw, src);
        }
        // B: pre-swizzled 4KB tile, linear copy (256 x 16B chunks, one per thread).
        const char* wsrc = reinterpret_cast<const char*>(g_wpk) + ((size_t)rblk * PAIRS + p) * 4096;
        uint32_t bbase = sb + SMEM_B0 + p * B_STRIDE;
        cp_async16(bbase + tid * 16, wsrc + tid * 16);
        cp_commit();
    }

    float acc[4][4];
#pragma unroll
    for (int i = 0; i < 4; i++)
#pragma unroll
        for (int j = 0; j < 4; j++) acc[i][j] = 0.0f;

    do_stage<0>(sb, wid, lane, acc);
    do_stage<1>(sb, wid, lane, acc);
    do_stage<2>(sb, wid, lane, acc);
    do_stage<3>(sb, wid, lane, acc);
    do_stage<4>(sb, wid, lane, acc);
    do_stage<5>(sb, wid, lane, acc);
    do_stage<6>(sb, wid, lane, acc);

    // Epilogue: c fragment -> global, + bias.
    // Thread holds rows (grp, grp+8) x cols (2q, 2q+1) per n-tile.
    int grp = lane >> 2, qid = lane & 3;
    int row0 = mt * 128 + wid * 16 + grp;
    float* obase = out + (size_t)row0 * NCOL + rblk * BS;
    const float* bb = bias + rblk * BS;
#pragma unroll
    for (int nt = 0; nt < 4; nt++) {
        int col = nt * 8 + 2 * qid;
        float2 bv = *reinterpret_cast<const float2*>(bb + col);
        float2 v0 = make_float2(acc[nt][0] + bv.x, acc[nt][1] + bv.y);
        float2 v1 = make_float2(acc[nt][2] + bv.x, acc[nt][3] + bv.y);
        *reinterpret_cast<float2*>(obase + col) = v0;
        *reinterpret_cast<float2*>(obase + 8 * (size_t)NCOL + col) = v1;
    }
}

// ---------------- launch ----------------
extern "C" void kernel_launch(void* const* d_in, const int* in_sizes, int n_in,
                              void* d_out, int out_size) {
    const float* x      = (const float*)d_in[0];
    const int*   crow   = (const int*)d_in[1];
    const int*   cols   = (const int*)d_in[2];
    const float* mask   = (const float*)d_in[3];
    const float* weight = (const float*)d_in[4];
    const float* bias   = (const float*)d_in[5];
    float* out = (float*)d_out;

    int batch = in_sizes[0] / NCOL;   // 2048
    int n8 = (batch * NCOL) / 8;

    cudaFuncSetAttribute(k_main, cudaFuncAttributeMaxDynamicSharedMemorySize, SMEM_TOTAL);

    k_convert_x<<<(n8 + 255) / 256, 256>>>(x, n8);
    k_prep_cols<<<(RB * SLOTS + 255) / 256, 256>>>(crow, cols);
    k_prep_w<<<RB * PAIRS, 256>>>(mask, weight, crow);

    dim3 grid(batch / 128, RB);
    k_main<<<grid, 256, SMEM_TOTAL>>>(bias, out);
}

// round 3
// speedup vs baseline: 1.3100x; 1.3100x over previous
#include <cuda_runtime.h>
#include <cuda_fp16.h>
#include <cstdint>

// ---------------- problem constants ----------------
static constexpr int BS    = 32;
static constexpr int RB    = 128;   // row blocks
static constexpr int CBLK  = 128;   // col blocks
static constexpr int PAIRS = 7;     // ceil(13/2) col-block pairs (padded)
static constexpr int SLOTS = 14;    // padded nnz slots per row
static constexpr int NCOL  = CBLK * BS;   // 4096
static constexpr int MAXBATCH = 2048;
static constexpr int MT    = 256;   // batch rows per CTA
static constexpr int STAGES = 3;    // ring depth

// ---------------- device scratch (static, no allocation) ----------------
__device__ __align__(16) __half g_x16[(size_t)MAXBATCH * NCOL];          // 16 MB fp16 x
__device__ __align__(16) __half g_wpk[(size_t)RB * PAIRS * 32 * 64];     // 3.5 MB packed, pre-swizzled w
__device__ int g_pcols[RB * SLOTS];

// ---------------- PTX helpers (baseline PTX only) ----------------
__device__ __forceinline__ uint32_t smem_u32(const void* p) {
    uint32_t a;
    asm("{ .reg .u64 t; cvta.to.shared.u64 t, %1; cvt.u32.u64 %0, t; }" : "=r"(a) : "l"(p));
    return a;
}
__device__ __forceinline__ void cp_async16(uint32_t dst, const void* src) {
    asm volatile("cp.async.cg.shared.global [%0], [%1], 16;" :: "r"(dst), "l"(src));
}
__device__ __forceinline__ void cp_commit() {
    asm volatile("cp.async.commit_group;" ::: "memory");
}
template <int N>
__device__ __forceinline__ void cp_wait() {
    asm volatile("cp.async.wait_group %0;" :: "n"(N) : "memory");
}

// ---------------- prep kernels ----------------
__global__ void k_convert_x(const float* __restrict__ x, int n8) {
    int i = blockIdx.x * blockDim.x + threadIdx.x;
    if (i >= n8) return;
    const float4* x4 = reinterpret_cast<const float4*>(x);
    float4 a = x4[2 * i], b = x4[2 * i + 1];
    union { __half2 h2[4]; uint4 v; } u;
    u.h2[0] = __floats2half2_rn(a.x, a.y);
    u.h2[1] = __floats2half2_rn(a.z, a.w);
    u.h2[2] = __floats2half2_rn(b.x, b.y);
    u.h2[3] = __floats2half2_rn(b.z, b.w);
    reinterpret_cast<uint4*>(g_x16)[i] = u.v;
}

__global__ void k_prep_cols(const int* __restrict__ crow, const int* __restrict__ cols) {
    int i = blockIdx.x * blockDim.x + threadIdx.x;
    if (i >= RB * SLOTS) return;
    int r = i / SLOTS, s = i % SLOTS;
    int beg = crow[r];
    int len = crow[r + 1] - beg;
    g_pcols[i] = (s < len) ? cols[beg + s] : 0;
}

// Packed, masked, fp16, SW128-pre-swizzled weights (4KB tile per (rblk,pair)).
__global__ void k_prep_w(const float* __restrict__ mask, const float* __restrict__ w,
                         const int* __restrict__ crow) {
    int tile = blockIdx.x;             // rblk*PAIRS + p
    int rblk = tile / PAIRS, p = tile % PAIRS;
    int q = threadIdx.x;               // 0..255, one 16B chunk each
    int n = q >> 3;                    // output row 0..31
    int m = q & 7;                     // 16B chunk within the 128B row
    int s = m >> 2;                    // which nnz block of the pair
    int kib = (m & 3) * 8;             // k within the 32-wide block
    int beg = crow[rblk];
    int len = crow[rblk + 1] - beg;
    int slot = 2 * p + s;
    bool valid = slot < len;
    long j = beg + slot;
    union { __half h[8]; uint4 v; } u;
#pragma unroll
    for (int i = 0; i < 8; i++) {
        float f = 0.0f;
        if (valid) {
            long e = j * 1024 + n * 32 + kib + i;
            f = mask[e] * w[e];
        }
        u.h[i] = __float2half_rn(f);
    }
    uint32_t off = (uint32_t)(n * 128 + m * 16);
    uint32_t sw = off ^ ((off >> 3) & 0x70);
    char* dst = reinterpret_cast<char*>(g_wpk) + (size_t)tile * 4096 + sw;
    *reinterpret_cast<uint4*>(dst) = u.v;
}

// ---------------- main kernel ----------------
static constexpr int A_BYTES    = MT * 128;                 // 32 KB per stage
static constexpr int B_BYTES    = 32 * 128;                 // 4 KB per stage
static constexpr int STG_STRIDE = A_BYTES + B_BYTES;        // 36 KB
static constexpr int SMEM_TOTAL = STAGES * STG_STRIDE;      // 108 KB

// Issue cp.async for stage p into ring slot.
__device__ __forceinline__ void issue_stage(uint32_t sb, int slot, int p, int tid,
                                            const __half* xb, const int* pc, int rblk) {
    int c0 = __ldg(pc + 2 * p);
    int c1 = __ldg(pc + 2 * p + 1);
    uint32_t abase = sb + slot * STG_STRIDE;
    // A: MT rows x 128B (two gathered 32-elem fp16 col blocks), SW128-swizzled.
#pragma unroll
    for (int t = tid; t < MT * 8; t += 256) {
        int q = t & 3;          // 16B chunk within 64B half
        int h = (t >> 2) & 1;   // which col block of the pair
        int r = t >> 3;         // batch row within tile
        const __half* src = xb + (size_t)r * NCOL + (h ? c1 : c0) * BS + q * 8;
        uint32_t off = (uint32_t)(r * 128 + h * 64 + q * 16);
        uint32_t sw = off ^ ((off >> 3) & 0x70);
        cp_async16(abase + sw, src);
    }
    // B: pre-swizzled 4KB tile, linear copy (one 16B chunk per thread).
    const char* wsrc = reinterpret_cast<const char*>(g_wpk) + ((size_t)rblk * PAIRS + p) * 4096;
    cp_async16(abase + A_BYTES + tid * 16, wsrc + tid * 16);
    cp_commit();
}

// Compute one stage (K=64) from ring slot. Each warp: two m16 tiles x four n8 tiles.
__device__ __forceinline__ void compute_stage(uint32_t sb, int slot, int wid, int lane,
                                              float acc[2][4][4]) {
    uint32_t abase = sb + slot * STG_STRIDE;
    uint32_t bbase = abase + A_BYTES;

    int arow = lane & 15;
    int akb  = lane >> 4;
    // B ldmatrix.x4: mat0 n0-7@k0, mat1 n0-7@k8, mat2 n8-15@k0, mat3 n8-15@k8.
    int bn  = (lane & 7) + ((lane >> 4) << 3);
    int bkb = (lane >> 3) & 1;

#pragma unroll
    for (int ks = 0; ks < 4; ks++) {
        uint32_t b[2][4];
#pragma unroll
        for (int h = 0; h < 2; h++) {
            uint32_t bo = (uint32_t)((bn + h * 16) * 128 + ks * 32 + bkb * 16);
            uint32_t baddr = bbase + (bo ^ ((bo >> 3) & 0x70));
            asm volatile("ldmatrix.sync.aligned.m8n8.x4.shared.b16 {%0,%1,%2,%3}, [%4];"
                         : "=r"(b[h][0]), "=r"(b[h][1]), "=r"(b[h][2]), "=r"(b[h][3])
                         : "r"(baddr));
        }
#pragma unroll
        for (int mi = 0; mi < 2; mi++) {
            uint32_t ao = (uint32_t)((mi * 128 + wid * 16 + arow) * 128 + akb * 16 + ks * 32);
            uint32_t aaddr = abase + (ao ^ ((ao >> 3) & 0x70));
            uint32_t a0, a1, a2, a3;
            asm volatile("ldmatrix.sync.aligned.m8n8.x4.shared.b16 {%0,%1,%2,%3}, [%4];"
                         : "=r"(a0), "=r"(a1), "=r"(a2), "=r"(a3) : "r"(aaddr));
#pragma unroll
            for (int nt = 0; nt < 4; nt++) {
                uint32_t b0 = b[nt >> 1][(nt & 1) * 2 + 0];
                uint32_t b1 = b[nt >> 1][(nt & 1) * 2 + 1];
                asm volatile(
                    "mma.sync.aligned.m16n8k16.row.col.f32.f16.f16.f32 "
                    "{%0,%1,%2,%3}, {%4,%5,%6,%7}, {%8,%9}, {%0,%1,%2,%3};"
                    : "+f"(acc[mi][nt][0]), "+f"(acc[mi][nt][1]),
                      "+f"(acc[mi][nt][2]), "+f"(acc[mi][nt][3])
                    : "r"(a0), "r"(a1), "r"(a2), "r"(a3), "r"(b0), "r"(b1));
            }
        }
    }
}

template <int P>
__device__ __forceinline__ void pipeline_stage(uint32_t sb, int wid, int lane, int tid,
                                               const __half* xb, const int* pc, int rblk,
                                               float acc[2][4][4]) {
    // groups issued so far = min(PAIRS, P+STAGES); need groups 0..P done.
    constexpr int WAITN = (PAIRS - 1 - P < STAGES - 1) ? (PAIRS - 1 - P) : (STAGES - 1);
    cp_wait<WAITN>();
    __syncthreads();
    compute_stage(sb, P % STAGES, wid, lane, acc);
    if (P + STAGES < PAIRS) {
        __syncthreads();   // all warps done reading this slot
        issue_stage(sb, P % STAGES, P + STAGES, tid, xb, pc, rblk);
    }
}

__global__ void __launch_bounds__(256, 2)
k_main(const float* __restrict__ bias, float* __restrict__ out) {
    extern __shared__ char smem[];
    uint32_t sb = smem_u32(smem);
    int tid = threadIdx.x;
    int wid = tid >> 5, lane = tid & 31;
    int mt = blockIdx.x;       // batch tile of MT rows
    int rblk = blockIdx.y;     // row block

    const __half* xb = g_x16 + (size_t)mt * MT * NCOL;
    const int* pc = g_pcols + rblk * SLOTS;

    // Prime the ring.
#pragma unroll
    for (int p = 0; p < STAGES; p++)
        issue_stage(sb, p, p, tid, xb, pc, rblk);

    float acc[2][4][4];
#pragma unroll
    for (int m = 0; m < 2; m++)
#pragma unroll
        for (int i = 0; i < 4; i++)
#pragma unroll
            for (int j = 0; j < 4; j++) acc[m][i][j] = 0.0f;

    pipeline_stage<0>(sb, wid, lane, tid, xb, pc, rblk, acc);
    pipeline_stage<1>(sb, wid, lane, tid, xb, pc, rblk, acc);
    pipeline_stage<2>(sb, wid, lane, tid, xb, pc, rblk, acc);
    pipeline_stage<3>(sb, wid, lane, tid, xb, pc, rblk, acc);
    pipeline_stage<4>(sb, wid, lane, tid, xb, pc, rblk, acc);
    pipeline_stage<5>(sb, wid, lane, tid, xb, pc, rblk, acc);
    pipeline_stage<6>(sb, wid, lane, tid, xb, pc, rblk, acc);

    // Epilogue: c fragments -> global, + bias.
    int grp = lane >> 2, qid = lane & 3;
    const float* bb = bias + rblk * BS;
#pragma unroll
    for (int mi = 0; mi < 2; mi++) {
        int row0 = mt * MT + mi * 128 + wid * 16 + grp;
        float* obase = out + (size_t)row0 * NCOL + rblk * BS;
#pragma unroll
        for (int nt = 0; nt < 4; nt++) {
            int col = nt * 8 + 2 * qid;
            float2 bv = *reinterpret_cast<const float2*>(bb + col);
            float2 v0 = make_float2(acc[mi][nt][0] + bv.x, acc[mi][nt][1] + bv.y);
            float2 v1 = make_float2(acc[mi][nt][2] + bv.x, acc[mi][nt][3] + bv.y);
            *reinterpret_cast<float2*>(obase + col) = v0;
            *reinterpret_cast<float2*>(obase + 8 * (size_t)NCOL + col) = v1;
        }
    }
}

// ---------------- launch ----------------
extern "C" void kernel_launch(void* const* d_in, const int* in_sizes, int n_in,
                              void* d_out, int out_size) {
    const float* x      = (const float*)d_in[0];
    const int*   crow   = (const int*)d_in[1];
    const int*   cols   = (const int*)d_in[2];
    const float* mask   = (const float*)d_in[3];
    const float* weight = (const float*)d_in[4];
    const float* bias   = (const float*)d_in[5];
    float* out = (float*)d_out;

    int batch = in_sizes[0] / NCOL;   // 2048
    int n8 = (batch * NCOL) / 8;

    cudaFuncSetAttribute(k_main, cudaFuncAttributeMaxDynamicSharedMemorySize, SMEM_TOTAL);

    k_convert_x<<<(n8 + 255) / 256, 256>>>(x, n8);
    k_prep_cols<<<(RB * SLOTS + 255) / 256, 256>>>(crow, cols);
    k_prep_w<<<RB * PAIRS, 256>>>(mask, weight, crow);

    dim3 grid(batch / MT, RB);
    k_main<<<grid, 256, SMEM_TOTAL>>>(bias, out);
}

// round 4
// speedup vs baseline: 1.3723x; 1.0476x over previous
#include <cuda_runtime.h>
#include <cuda_fp16.h>
#include <cstdint>

// ---------------- problem constants ----------------
static constexpr int BS    = 32;
static constexpr int RB    = 128;   // row blocks
static constexpr int CBLK  = 128;   // col blocks
static constexpr int PAIRS = 7;     // ceil(13/2) col-block pairs (padded)
static constexpr int SLOTS = 14;    // padded nnz slots per row
static constexpr int NCOL  = CBLK * BS;   // 4096
static constexpr int MAXBATCH = 2048;
static constexpr int MT    = 256;   // batch rows per CTA
static constexpr int TPB   = 128;   // 4 warps; each warp computes m64 x n32
static constexpr int STAGES = 2;    // ring depth

// ---------------- device scratch (static, no allocation) ----------------
__device__ __align__(16) __half g_x16[(size_t)MAXBATCH * NCOL];          // 16 MB fp16 x
__device__ __align__(16) __half g_wpk[(size_t)RB * PAIRS * 32 * 64];     // 3.5 MB packed, pre-swizzled w
__device__ int g_pcols[RB * SLOTS];

// ---------------- PTX helpers (baseline PTX only) ----------------
__device__ __forceinline__ uint32_t smem_u32(const void* p) {
    uint32_t a;
    asm("{ .reg .u64 t; cvta.to.shared.u64 t, %1; cvt.u32.u64 %0, t; }" : "=r"(a) : "l"(p));
    return a;
}
__device__ __forceinline__ void cp_async16(uint32_t dst, const void* src) {
    asm volatile("cp.async.cg.shared.global [%0], [%1], 16;" :: "r"(dst), "l"(src));
}
__device__ __forceinline__ void cp_commit() {
    asm volatile("cp.async.commit_group;" ::: "memory");
}
template <int N>
__device__ __forceinline__ void cp_wait() {
    asm volatile("cp.async.wait_group %0;" :: "n"(N) : "memory");
}

// ---------------- prep kernels ----------------
__global__ void k_convert_x(const float* __restrict__ x, int n8) {
    int i = blockIdx.x * blockDim.x + threadIdx.x;
    if (i >= n8) return;
    const float4* x4 = reinterpret_cast<const float4*>(x);
    float4 a = x4[2 * i], b = x4[2 * i + 1];
    union { __half2 h2[4]; uint4 v; } u;
    u.h2[0] = __floats2half2_rn(a.x, a.y);
    u.h2[1] = __floats2half2_rn(a.z, a.w);
    u.h2[2] = __floats2half2_rn(b.x, b.y);
    u.h2[3] = __floats2half2_rn(b.z, b.w);
    reinterpret_cast<uint4*>(g_x16)[i] = u.v;
}

__global__ void k_prep_cols(const int* __restrict__ crow, const int* __restrict__ cols) {
    int i = blockIdx.x * blockDim.x + threadIdx.x;
    if (i >= RB * SLOTS) return;
    int r = i / SLOTS, s = i % SLOTS;
    int beg = crow[r];
    int len = crow[r + 1] - beg;
    g_pcols[i] = (s < len) ? cols[beg + s] : 0;
}

// Packed, masked, fp16, SW128-pre-swizzled weights (4KB tile per (rblk,pair)).
__global__ void k_prep_w(const float* __restrict__ mask, const float* __restrict__ w,
                         const int* __restrict__ crow) {
    int tile = blockIdx.x;             // rblk*PAIRS + p
    int rblk = tile / PAIRS, p = tile % PAIRS;
    int q = threadIdx.x;               // 0..255, one 16B chunk each
    int n = q >> 3;                    // output row 0..31
    int m = q & 7;                     // 16B chunk within the 128B row
    int s = m >> 2;                    // which nnz block of the pair
    int kib = (m & 3) * 8;             // k within the 32-wide block
    int beg = crow[rblk];
    int len = crow[rblk + 1] - beg;
    int slot = 2 * p + s;
    bool valid = slot < len;
    long j = beg + slot;
    union { __half h[8]; uint4 v; } u;
#pragma unroll
    for (int i = 0; i < 8; i++) {
        float f = 0.0f;
        if (valid) {
            long e = j * 1024 + n * 32 + kib + i;
            f = mask[e] * w[e];
        }
        u.h[i] = __float2half_rn(f);
    }
    uint32_t off = (uint32_t)(n * 128 + m * 16);
    uint32_t sw = off ^ ((off >> 3) & 0x70);
    char* dst = reinterpret_cast<char*>(g_wpk) + (size_t)tile * 4096 + sw;
    *reinterpret_cast<uint4*>(dst) = u.v;
}

// ---------------- main kernel ----------------
static constexpr int A_BYTES    = MT * 128;                 // 32 KB per stage
static constexpr int B_BYTES    = 32 * 128;                 // 4 KB per stage
static constexpr int STG_STRIDE = A_BYTES + B_BYTES;        // 36 KB
static constexpr int SMEM_TOTAL = STAGES * STG_STRIDE;      // 72 KB -> 3 CTAs/SM

// Issue cp.async for stage p into ring slot.
__device__ __forceinline__ void issue_stage(uint32_t sb, int slot, int p, int tid,
                                            const __half* xb, const int* pc, int rblk) {
    int c0 = __ldg(pc + 2 * p);
    int c1 = __ldg(pc + 2 * p + 1);
    uint32_t abase = sb + slot * STG_STRIDE;
    // A: MT rows x 128B (two gathered 32-elem fp16 col blocks), SW128-swizzled.
#pragma unroll
    for (int t = tid; t < MT * 8; t += TPB) {
        int q = t & 3;          // 16B chunk within 64B half
        int h = (t >> 2) & 1;   // which col block of the pair
        int r = t >> 3;         // batch row within tile
        const __half* src = xb + (size_t)r * NCOL + (h ? c1 : c0) * BS + q * 8;
        uint32_t off = (uint32_t)(r * 128 + h * 64 + q * 16);
        uint32_t sw = off ^ ((off >> 3) & 0x70);
        cp_async16(abase + sw, src);
    }
    // B: pre-swizzled 4KB tile, linear copy (two 16B chunks per thread).
    const char* wsrc = reinterpret_cast<const char*>(g_wpk) + ((size_t)rblk * PAIRS + p) * 4096;
#pragma unroll
    for (int t = tid; t < 256; t += TPB)
        cp_async16(abase + A_BYTES + t * 16, wsrc + t * 16);
    cp_commit();
}

// Compute one stage (K=64). Each warp: FOUR m16 tiles (m64) x four n8 tiles,
// reusing one set of B fragments across all 4 m-tiles.
__device__ __forceinline__ void compute_stage(uint32_t sb, int slot, int wid, int lane,
                                              float acc[4][4][4]) {
    uint32_t abase = sb + slot * STG_STRIDE;
    uint32_t bbase = abase + A_BYTES;

    int arow = lane & 15;
    int akb  = lane >> 4;
    // B ldmatrix.x4: mat0 n0-7@k0, mat1 n0-7@k8, mat2 n8-15@k0, mat3 n8-15@k8.
    int bn  = (lane & 7) + ((lane >> 4) << 3);
    int bkb = (lane >> 3) & 1;

#pragma unroll
    for (int ks = 0; ks < 4; ks++) {
        uint32_t b[2][4];
#pragma unroll
        for (int h = 0; h < 2; h++) {
            uint32_t bo = (uint32_t)((bn + h * 16) * 128 + ks * 32 + bkb * 16);
            uint32_t baddr = bbase + (bo ^ ((bo >> 3) & 0x70));
            asm volatile("ldmatrix.sync.aligned.m8n8.x4.shared.b16 {%0,%1,%2,%3}, [%4];"
                         : "=r"(b[h][0]), "=r"(b[h][1]), "=r"(b[h][2]), "=r"(b[h][3])
                         : "r"(baddr));
        }
#pragma unroll
        for (int mi = 0; mi < 4; mi++) {
            uint32_t ao = (uint32_t)((mi * 64 + wid * 16 + arow) * 128 + akb * 16 + ks * 32);
            uint32_t aaddr = abase + (ao ^ ((ao >> 3) & 0x70));
            uint32_t a0, a1, a2, a3;
            asm volatile("ldmatrix.sync.aligned.m8n8.x4.shared.b16 {%0,%1,%2,%3}, [%4];"
                         : "=r"(a0), "=r"(a1), "=r"(a2), "=r"(a3) : "r"(aaddr));
#pragma unroll
            for (int nt = 0; nt < 4; nt++) {
                uint32_t b0 = b[nt >> 1][(nt & 1) * 2 + 0];
                uint32_t b1 = b[nt >> 1][(nt & 1) * 2 + 1];
                asm volatile(
                    "mma.sync.aligned.m16n8k16.row.col.f32.f16.f16.f32 "
                    "{%0,%1,%2,%3}, {%4,%5,%6,%7}, {%8,%9}, {%0,%1,%2,%3};"
                    : "+f"(acc[mi][nt][0]), "+f"(acc[mi][nt][1]),
                      "+f"(acc[mi][nt][2]), "+f"(acc[mi][nt][3])
                    : "r"(a0), "r"(a1), "r"(a2), "r"(a3), "r"(b0), "r"(b1));
            }
        }
    }
}

__global__ void __launch_bounds__(TPB, 3)
k_main(const float* __restrict__ bias, float* __restrict__ out) {
    extern __shared__ char smem[];
    uint32_t sb = smem_u32(smem);
    int tid = threadIdx.x;
    int wid = tid >> 5, lane = tid & 31;
    int mt = blockIdx.x;       // batch tile of MT rows
    int rblk = blockIdx.y;     // row block

    const __half* xb = g_x16 + (size_t)mt * MT * NCOL;
    const int* pc = g_pcols + rblk * SLOTS;

    // Prime the 2-deep ring.
    issue_stage(sb, 0, 0, tid, xb, pc, rblk);
    issue_stage(sb, 1, 1, tid, xb, pc, rblk);

    float acc[4][4][4];
#pragma unroll
    for (int m = 0; m < 4; m++)
#pragma unroll
        for (int i = 0; i < 4; i++)
#pragma unroll
            for (int j = 0; j < 4; j++) acc[m][i][j] = 0.0f;

    for (int p = 0; p < PAIRS - 1; p++) {
        cp_wait<1>();
        __syncthreads();
        compute_stage(sb, p & 1, wid, lane, acc);
        if (p + STAGES < PAIRS) {
            __syncthreads();   // all warps done reading this slot
            issue_stage(sb, p & 1, p + STAGES, tid, xb, pc, rblk);
        }
    }
    cp_wait<0>();
    __syncthreads();
    compute_stage(sb, (PAIRS - 1) & 1, wid, lane, acc);

    // Epilogue: c fragments -> global, + bias.
    int grp = lane >> 2, qid = lane & 3;
    const float* bb = bias + rblk * BS;
#pragma unroll
    for (int mi = 0; mi < 4; mi++) {
        int row0 = mt * MT + mi * 64 + wid * 16 + grp;
        float* obase = out + (size_t)row0 * NCOL + rblk * BS;
#pragma unroll
        for (int nt = 0; nt < 4; nt++) {
            int col = nt * 8 + 2 * qid;
            float2 bv = *reinterpret_cast<const float2*>(bb + col);
            float2 v0 = make_float2(acc[mi][nt][0] + bv.x, acc[mi][nt][1] + bv.y);
            float2 v1 = make_float2(acc[mi][nt][2] + bv.x, acc[mi][nt][3] + bv.y);
            *reinterpret_cast<float2*>(obase + col) = v0;
            *reinterpret_cast<float2*>(obase + 8 * (size_t)NCOL + col) = v1;
        }
    }
}

// ---------------- launch ----------------
extern "C" void kernel_launch(void* const* d_in, const int* in_sizes, int n_in,
                              void* d_out, int out_size) {
    const float* x      = (const float*)d_in[0];
    const int*   crow   = (const int*)d_in[1];
    const int*   cols   = (const int*)d_in[2];
    const float* mask   = (const float*)d_in[3];
    const float* weight = (const float*)d_in[4];
    const float* bias   = (const float*)d_in[5];
    float* out = (float*)d_out;

    int batch = in_sizes[0] / NCOL;   // 2048
    int n8 = (batch * NCOL) / 8;

    cudaFuncSetAttribute(k_main, cudaFuncAttributeMaxDynamicSharedMemorySize, SMEM_TOTAL);

    k_convert_x<<<(n8 + 255) / 256, 256>>>(x, n8);
    k_prep_cols<<<(RB * SLOTS + 255) / 256, 256>>>(crow, cols);
    k_prep_w<<<RB * PAIRS, 256>>>(mask, weight, crow);

    dim3 grid(batch / MT, RB);
    k_main<<<grid, TPB, SMEM_TOTAL>>>(bias, out);
}